// round 8
// baseline (speedup 1.0000x reference)
#include <cuda_runtime.h>
#include <cuda_bf16.h>
#include <cstdint>
#include <math.h>

// Problem constants
#define BATCH  4
#define S_LEN  2048
#define NHEAD  12
#define DHEAD  100
#define HIDDEN 1200
#define M_TOT  (BATCH * S_LEN)          // 8192
#define BH     (BATCH * NHEAD)          // 48
#define PPAIR  608                      // padded K in bf16-pairs (1216 vals)
#define PROWSW 1280                     // weight rows padded
#define NCHUNK 19                       // 1216 / 64

// ---------------------------------------------------------------------------
// Interchange buffers: uint2 = (hi bf16x2, lo bf16x2) for one k-pair.
// ---------------------------------------------------------------------------
__device__ __align__(16) uint2 g_x[M_TOT * PPAIR];
__device__ __align__(16) uint2 g_w[4][PROWSW * PPAIR];
// Q,K: (bh, s, 52 pairs along d; pairs 50,51 zero)
__device__ __align__(16) uint2 g_q[BH * S_LEN * 52];
__device__ __align__(16) uint2 g_k[BH * S_LEN * 52];
// V^T: (bh, 104 d-rows, 1024 s-pairs; d rows 100..103 zero)
__device__ __align__(16) uint2 g_vt[BH * 104 * 1024];
// O: padded (8192, 608 pairs; pairs 600..607 zero)
__device__ __align__(16) uint2 g_o[M_TOT * PPAIR];

// ---------------------------------------------------------------------------
// BF16 helpers + mma.sync
// ---------------------------------------------------------------------------
__device__ __forceinline__ unsigned cvt2(float even, float odd) {
    unsigned r;
    asm("cvt.rn.bf16x2.f32 %0, %1, %2;" : "=r"(r) : "f"(odd), "f"(even));
    return r;
}
__device__ __forceinline__ float bf_lo(unsigned p) { return __uint_as_float(p << 16); }
__device__ __forceinline__ float bf_hi(unsigned p) { return __uint_as_float(p & 0xFFFF0000u); }
__device__ __forceinline__ void split2(float e, float o, unsigned& h, unsigned& l) {
    h = cvt2(e, o);
    l = cvt2(e - bf_lo(h), o - bf_hi(h));
}
__device__ __forceinline__ void mma16(float* c, const unsigned* a, const unsigned* b) {
    asm volatile(
        "mma.sync.aligned.m16n8k16.row.col.f32.bf16.bf16.f32 "
        "{%0,%1,%2,%3}, {%4,%5,%6,%7}, {%8,%9}, {%0,%1,%2,%3};\n"
        : "+f"(c[0]), "+f"(c[1]), "+f"(c[2]), "+f"(c[3])
        : "r"(a[0]), "r"(a[1]), "r"(a[2]), "r"(a[3]), "r"(b[0]), "r"(b[1]));
}
__device__ __forceinline__ void mma8b(float* c, const unsigned* a, unsigned b) {
    asm volatile(
        "mma.sync.aligned.m16n8k8.row.col.f32.bf16.bf16.f32 "
        "{%0,%1,%2,%3}, {%4,%5}, {%6}, {%0,%1,%2,%3};\n"
        : "+f"(c[0]), "+f"(c[1]), "+f"(c[2]), "+f"(c[3])
        : "r"(a[0]), "r"(a[1]), "r"(b));
}
__device__ __forceinline__ void cpa16(uint32_t s_addr, const void* g) {
    asm volatile("cp.async.cg.shared.global [%0], [%1], 16;" :: "r"(s_addr), "l"(g));
}
__device__ __forceinline__ uint32_t smem_u32p(const void* p) {
    uint32_t a;
    asm("{ .reg .u64 t; cvta.to.shared.u64 t, %1; cvt.u32.u64 %0, t; }" : "=r"(a) : "l"(p));
    return a;
}

// ---------------------------------------------------------------------------
// Prep: fp32 -> interleaved (hi,lo) bf16x2 pairs, zero-padded
// ---------------------------------------------------------------------------
__global__ void split_pad_kernel(const float* __restrict__ src, uint2* __restrict__ dst,
                                 int rows, int cols, int total)
{
    const int i = blockIdx.x * 256 + threadIdx.x;
    if (i >= total) return;
    const int r = i / PPAIR;
    const int p = i - r * PPAIR;
    const int c = 2 * p;
    const float v0 = (r < rows && c     < cols) ? src[(long)r * cols + c]     : 0.f;
    const float v1 = (r < rows && c + 1 < cols) ? src[(long)r * cols + c + 1] : 0.f;
    unsigned h, l;
    split2(v0, v1, h, l);
    dst[i] = make_uint2(h, l);
}

// Zero pad regions: Q/K pairs 50,51; Vt d-rows 100..103; O pairs 600..607
__global__ void init_pads_kernel(uint2* q, uint2* k, uint2* vt, uint2* o)
{
    const int i = blockIdx.x * 256 + threadIdx.x;
    const uint2 z = make_uint2(0u, 0u);
    if (i < BH * S_LEN * 2) {
        const long a = (long)(i >> 1) * 52 + 50 + (i & 1);
        q[a] = z; k[a] = z;
    }
    if (i < BH * 4 * 1024) {
        const int bh = i >> 12;
        vt[((long)bh * 104 + 100) * 1024 + (i & 4095)] = z;
    }
    if (i < M_TOT * 8) {
        o[(long)(i >> 3) * PPAIR + 600 + (i & 7)] = z;
    }
}

// ---------------------------------------------------------------------------
// GEMM v2: cp.async 2-stage pipeline. C[m,n] = sum_k A[m,k]*W[n,k].
// 512 threads, warp grid 4x4 (warp tile 32x32), tile 128x128, BK=64 (32 pairs).
// smem per stage: A[128][36] uint2 + B[128][36] uint2 (stride 36 pairs = 72 u32,
// 72 mod 32 == 8 -> conflict-free LDS.64 fragment loads).
// mode 0: f32 row-major (M,1200); 1: Q/K layout; 3: V^T layout.
// ---------------------------------------------------------------------------
#define GRS 36                          // uint2 row stride
#define GT_A_BYTES (128 * GRS * 8)      // 36864
#define GT_STAGE   (2 * GT_A_BYTES)     // 73728 (A then B)
#define GT_SMEM    (2 * GT_STAGE)       // 147456

__global__ __launch_bounds__(512, 1) void gemm_pipe_kernel(
    const uint2* __restrict__ Ag, const uint2* __restrict__ Bg,
    float* __restrict__ Cf, uint2* __restrict__ Cqk, uint2* __restrict__ Cvt,
    int mode)
{
    extern __shared__ unsigned char smb[];
    const uint32_t sbase = smem_u32p(smb);

    const int tid  = threadIdx.x;
    const int lane = tid & 31;
    const int warp = tid >> 5;
    const int wm   = warp >> 2;     // 0..3
    const int wn   = warp & 3;      // 0..3
    const int m0   = blockIdx.x * 128;
    const int n0   = blockIdx.y * 128;
    const int lr   = lane >> 2;
    const int lc   = lane & 3;

    float acc[2][4][4];
#pragma unroll
    for (int i = 0; i < 2; i++)
#pragma unroll
        for (int j = 0; j < 4; j++)
#pragma unroll
            for (int r = 0; r < 4; r++) acc[i][j][r] = 0.f;

    // loader indices: 2048 16B-chunks per operand per stage, 4 per thread
    const int lrow = tid >> 4;          // 0..31
    const int lc16 = tid & 15;          // 16B chunk in row (32 pairs = 16 chunks)

    // issue stage load for chunk ch into buffer st
#define GLOAD(ch, st) do {                                                          \
        const uint32_t ab = sbase + (st) * GT_STAGE;                                \
        const uint32_t bb = ab + GT_A_BYTES;                                        \
        _Pragma("unroll")                                                           \
        for (int q_ = 0; q_ < 4; q_++) {                                            \
            const int row = lrow + q_ * 32;                                         \
            cpa16(ab + row * (GRS * 8) + lc16 * 16,                                 \
                  Ag + (long)(m0 + row) * PPAIR + (ch) * 32 + lc16 * 2);            \
            cpa16(bb + row * (GRS * 8) + lc16 * 16,                                 \
                  Bg + (long)(n0 + row) * PPAIR + (ch) * 32 + lc16 * 2);            \
        }                                                                           \
    } while (0)

    GLOAD(0, 0);
    asm volatile("cp.async.commit_group;");

    const uint2* As;
    const uint2* Bs;
    for (int ch = 0; ch < NCHUNK; ch++) {
        if (ch + 1 < NCHUNK) GLOAD(ch + 1, (ch + 1) & 1);
        asm volatile("cp.async.commit_group;");
        asm volatile("cp.async.wait_group 1;");
        __syncthreads();

        As = (const uint2*)(smb + (ch & 1) * GT_STAGE);
        Bs = (const uint2*)(smb + (ch & 1) * GT_STAGE + GT_A_BYTES);

#pragma unroll
        for (int s = 0; s < 4; s++) {
            unsigned bhv[4][2], blv[4][2];
#pragma unroll
            for (int nt = 0; nt < 4; nt++) {
                const int n = wn * 32 + nt * 8 + lr;
                const uint2 p0 = Bs[n * GRS + 8 * s + lc];
                const uint2 p1 = Bs[n * GRS + 8 * s + 4 + lc];
                bhv[nt][0] = p0.x; bhv[nt][1] = p1.x;
                blv[nt][0] = p0.y; blv[nt][1] = p1.y;
            }
#pragma unroll
            for (int mt = 0; mt < 2; mt++) {
                const int m = wm * 32 + mt * 16 + lr;
                const uint2 a0 = As[m * GRS + 8 * s + lc];
                const uint2 a1 = As[(m + 8) * GRS + 8 * s + lc];
                const uint2 a2 = As[m * GRS + 8 * s + 4 + lc];
                const uint2 a3 = As[(m + 8) * GRS + 8 * s + 4 + lc];
                unsigned ah[4] = {a0.x, a1.x, a2.x, a3.x};
                unsigned al[4] = {a0.y, a1.y, a2.y, a3.y};
#pragma unroll
                for (int nt = 0; nt < 4; nt++) {
                    mma16(acc[mt][nt], ah, bhv[nt]);
                    mma16(acc[mt][nt], ah, blv[nt]);
                    mma16(acc[mt][nt], al, bhv[nt]);
                }
            }
        }
        __syncthreads();
    }
#undef GLOAD

    // ---- Epilogue ----
    if (mode == 3) {
        // stage C fp32 in smem, transpose-store as V^T s-pairs
        float* Ct = (float*)smb;   // [128 n][129 m]
#pragma unroll
        for (int mt = 0; mt < 2; mt++)
#pragma unroll
            for (int nt = 0; nt < 4; nt++) {
                const int mL = wm * 32 + mt * 16 + lr;
                const int nL = wn * 32 + nt * 8 + lc * 2;
                Ct[(nL)     * 129 + mL]     = acc[mt][nt][0];
                Ct[(nL + 1) * 129 + mL]     = acc[mt][nt][1];
                Ct[(nL)     * 129 + mL + 8] = acc[mt][nt][2];
                Ct[(nL + 1) * 129 + mL + 8] = acc[mt][nt][3];
            }
        __syncthreads();
#pragma unroll
        for (int it = 0; it < 16; it++) {
            const int idx = tid + it * 512;    // 0..8191
            const int nL  = idx >> 6;          // 0..127
            const int mp  = idx & 63;          // m-pair
            const int n   = n0 + nL;
            if (n < HIDDEN) {
                const float c0 = Ct[nL * 129 + 2 * mp];
                const float c1 = Ct[nL * 129 + 2 * mp + 1];
                const int m = m0 + 2 * mp;
                const int b_ = m >> 11, s_ = m & (S_LEN - 1);
                const int h_ = n / DHEAD, d_ = n % DHEAD;
                unsigned h, l;
                split2(c0, c1, h, l);
                Cvt[((long)(b_ * NHEAD + h_) * 104 + d_) * 1024 + (s_ >> 1)] = make_uint2(h, l);
            }
        }
        return;
    }

#pragma unroll
    for (int mt = 0; mt < 2; mt++) {
#pragma unroll
        for (int nt = 0; nt < 4; nt++) {
            const int nn = n0 + wn * 32 + nt * 8 + lc * 2;
            if (nn >= HIDDEN) continue;
#pragma unroll
            for (int half = 0; half < 2; half++) {
                const int mm = m0 + wm * 32 + mt * 16 + lr + half * 8;
                const float c0 = acc[mt][nt][half * 2];
                const float c1 = acc[mt][nt][half * 2 + 1];
                if (mode == 0) {
                    *(float2*)&Cf[(long)mm * HIDDEN + nn] = make_float2(c0, c1);
                } else {
                    const int b_ = mm >> 11, s_ = mm & (S_LEN - 1);
                    const int h_ = nn / DHEAD, d_ = nn % DHEAD;
                    unsigned h, l;
                    split2(c0, c1, h, l);
                    Cqk[((long)(b_ * NHEAD + h_) * S_LEN + s_) * 52 + (d_ >> 1)] = make_uint2(h, l);
                }
            }
        }
    }
}

// ---------------------------------------------------------------------------
// Flash attention (bf16 3-mma). 256 threads, q-tile 128, kv 64.
// Interleaved (hi,lo) pairs in smem: one LDS.64 per fragment word-pair.
// Strides (u32): Q/K rows 104, V rows 72 -- both ≡ 8 (mod 32): conflict-free.
// ---------------------------------------------------------------------------
#define QSP 52     // Q/K uint2 row stride
#define VSP 36     // V uint2 row stride
#define QS_OFF   0         // u32 offsets
#define KS_OFF   13312
#define VS_OFF   19968
#define BIAS_OFF 27456
#define FL_SMEM_U32 27520
#define FL_SMEM_BYTES (FL_SMEM_U32 * 4)
#define NDT 13

__global__ __launch_bounds__(256, 2) void flash_kernel(
    const float* __restrict__ alibi, const float* __restrict__ mask,
    const int* __restrict__ layer_index,
    const uint2* __restrict__ qg, const uint2* __restrict__ kg,
    const uint2* __restrict__ vg, uint2* __restrict__ og)
{
    extern __shared__ unsigned smu[];
    uint2* Qs   = (uint2*)(smu + QS_OFF);   // [128][52]
    uint2* Ks   = (uint2*)(smu + KS_OFF);   // [64][52]
    uint2* Vs   = (uint2*)(smu + VS_OFF);   // [104][36]
    float* bias = (float*)(smu + BIAS_OFF);

    const int tid  = threadIdx.x;
    const int lane = tid & 31;
    const int w    = tid >> 5;
    const int lr   = lane >> 2;
    const int lc   = lane & 3;
    const int bh   = blockIdx.x;
    const int q0   = blockIdx.y * 128;
    const int b_   = bh / NHEAD;
    const int h_   = bh % NHEAD;

    const float inv = 1.f / (float)(layer_index[0] + 1);
    const float sc  = 10.f * inv;

    // Q tile copy (52 pairs/row = 26 uint4)
    {
        const uint2* qsrc = qg + ((long)bh * S_LEN + q0) * 52;
        for (int id = tid; id < 128 * 26; id += 256) {
            const int r = id / 26;
            const int c = (id % 26) * 2;
            *(uint4*)&Qs[r * QSP + c] = *(const uint4*)&qsrc[r * 52 + c];
        }
    }

    float oacc[NDT][4];
#pragma unroll
    for (int nt = 0; nt < NDT; nt++)
#pragma unroll
        for (int r = 0; r < 4; r++) oacc[nt][r] = 0.f;
    float mrow0 = -1e30f, mrow1 = -1e30f, lsum0 = 0.f, lsum1 = 0.f;

    const int ar = 16 * w + lr;

    for (int kt = 0; kt < S_LEN / 64; kt++) {
        const int k0g = kt * 64;
        __syncthreads();

        {
            const uint2* ksrc = kg + ((long)bh * S_LEN + k0g) * 52;
            for (int id = tid; id < 64 * 26; id += 256) {
                const int r = id / 26;
                const int c = (id % 26) * 2;
                *(uint4*)&Ks[r * QSP + c] = *(const uint4*)&ksrc[r * 52 + c];
            }
            const uint2* vsrc = vg + (long)bh * 104 * 1024 + (k0g >> 1);
            for (int id = tid; id < 104 * 16; id += 256) {
                const int d = id / 16;
                const int c = (id % 16) * 2;
                *(uint4*)&Vs[d * VSP + c] = *(const uint4*)&vsrc[d * 1024 + c];
            }
        }
        if (tid < 64) {
            const int t = k0g + tid;
            bias[tid] = alibi[(long)bh * S_LEN + t] * inv + mask[(long)b_ * S_LEN + t];
        }
        __syncthreads();

        // ---- S = Q K^T ----
        float sacc[8][4];
#pragma unroll
        for (int nt = 0; nt < 8; nt++)
#pragma unroll
            for (int r = 0; r < 4; r++) sacc[nt][r] = 0.f;

#pragma unroll
        for (int s = 0; s < 6; s++) {
            const uint2 a0 = Qs[ar * QSP + 8 * s + lc];
            const uint2 a1 = Qs[(ar + 8) * QSP + 8 * s + lc];
            const uint2 a2 = Qs[ar * QSP + 8 * s + 4 + lc];
            const uint2 a3 = Qs[(ar + 8) * QSP + 8 * s + 4 + lc];
            unsigned ah[4] = {a0.x, a1.x, a2.x, a3.x};
            unsigned al[4] = {a0.y, a1.y, a2.y, a3.y};
#pragma unroll
            for (int nt = 0; nt < 8; nt++) {
                const int bn = nt * 8 + lr;
                const uint2 k0p = Ks[bn * QSP + 8 * s + lc];
                const uint2 k1p = Ks[bn * QSP + 8 * s + 4 + lc];
                unsigned bh2[2] = {k0p.x, k1p.x};
                unsigned bl2[2] = {k0p.y, k1p.y};
                mma16(sacc[nt], ah, bh2);
                mma16(sacc[nt], ah, bl2);
                mma16(sacc[nt], al, bh2);
            }
        }
        {   // k8 tail (pairs 48..51; 50,51 zero)
            const uint2 t0 = Qs[ar * QSP + 48 + lc];
            const uint2 t1 = Qs[(ar + 8) * QSP + 48 + lc];
            unsigned ah2[2] = {t0.x, t1.x};
            unsigned al2[2] = {t0.y, t1.y};
#pragma unroll
            for (int nt = 0; nt < 8; nt++) {
                const int bn = nt * 8 + lr;
                const uint2 kp = Ks[bn * QSP + 48 + lc];
                mma8b(sacc[nt], ah2, kp.x);
                mma8b(sacc[nt], ah2, kp.y);
                mma8b(sacc[nt], al2, kp.x);
            }
        }

#pragma unroll
        for (int nt = 0; nt < 8; nt++) {
            const int col = nt * 8 + lc * 2;
            const float b0v = bias[col], b1v = bias[col + 1];
            sacc[nt][0] = sacc[nt][0] * sc + b0v;
            sacc[nt][1] = sacc[nt][1] * sc + b1v;
            sacc[nt][2] = sacc[nt][2] * sc + b0v;
            sacc[nt][3] = sacc[nt][3] * sc + b1v;
        }

        // ---- online softmax ----
        float rm0 = -1e30f, rm1 = -1e30f;
#pragma unroll
        for (int nt = 0; nt < 8; nt++) {
            rm0 = fmaxf(rm0, fmaxf(sacc[nt][0], sacc[nt][1]));
            rm1 = fmaxf(rm1, fmaxf(sacc[nt][2], sacc[nt][3]));
        }
        rm0 = fmaxf(rm0, __shfl_xor_sync(0xffffffffu, rm0, 1));
        rm0 = fmaxf(rm0, __shfl_xor_sync(0xffffffffu, rm0, 2));
        rm1 = fmaxf(rm1, __shfl_xor_sync(0xffffffffu, rm1, 1));
        rm1 = fmaxf(rm1, __shfl_xor_sync(0xffffffffu, rm1, 2));
        const float mn0 = fmaxf(mrow0, rm0);
        const float mn1 = fmaxf(mrow1, rm1);
        const float f0  = __expf(mrow0 - mn0);
        const float f1  = __expf(mrow1 - mn1);
        float rs0 = 0.f, rs1 = 0.f;
#pragma unroll
        for (int nt = 0; nt < 8; nt++) {
            sacc[nt][0] = __expf(sacc[nt][0] - mn0);
            sacc[nt][1] = __expf(sacc[nt][1] - mn0);
            sacc[nt][2] = __expf(sacc[nt][2] - mn1);
            sacc[nt][3] = __expf(sacc[nt][3] - mn1);
            rs0 += sacc[nt][0] + sacc[nt][1];
            rs1 += sacc[nt][2] + sacc[nt][3];
        }
        rs0 += __shfl_xor_sync(0xffffffffu, rs0, 1);
        rs0 += __shfl_xor_sync(0xffffffffu, rs0, 2);
        rs1 += __shfl_xor_sync(0xffffffffu, rs1, 1);
        rs1 += __shfl_xor_sync(0xffffffffu, rs1, 2);
        lsum0 = lsum0 * f0 + rs0;
        lsum1 = lsum1 * f1 + rs1;
        mrow0 = mn0;
        mrow1 = mn1;
#pragma unroll
        for (int nt = 0; nt < NDT; nt++) {
            oacc[nt][0] *= f0; oacc[nt][1] *= f0;
            oacc[nt][2] *= f1; oacc[nt][3] *= f1;
        }

        // ---- pack P to bf16 fragments (registers only) ----
        unsigned aH[8][2], aL[8][2];
#pragma unroll
        for (int nt = 0; nt < 8; nt++) {
            split2(sacc[nt][0], sacc[nt][1], aH[nt][0], aL[nt][0]);
            split2(sacc[nt][2], sacc[nt][3], aH[nt][1], aL[nt][1]);
        }

        // ---- O += P V ----
#pragma unroll
        for (int ks = 0; ks < 4; ks++) {
            unsigned pah[4], pal[4];
            pah[0] = aH[2 * ks][0];     pah[1] = aH[2 * ks][1];
            pah[2] = aH[2 * ks + 1][0]; pah[3] = aH[2 * ks + 1][1];
            pal[0] = aL[2 * ks][0];     pal[1] = aL[2 * ks][1];
            pal[2] = aL[2 * ks + 1][0]; pal[3] = aL[2 * ks + 1][1];
#pragma unroll
            for (int nt = 0; nt < NDT; nt++) {
                const int bn = nt * 8 + lr;
                const uint2 v0p = Vs[bn * VSP + 8 * ks + lc];
                const uint2 v1p = Vs[bn * VSP + 8 * ks + 4 + lc];
                unsigned bh2[2] = {v0p.x, v1p.x};
                unsigned bl2[2] = {v0p.y, v1p.y};
                mma16(oacc[nt], pah, bh2);
                mma16(oacc[nt], pah, bl2);
                mma16(oacc[nt], pal, bh2);
            }
        }
    }

    // ---- normalize + store O (interleaved pairs, padded GEMM-A layout) ----
    const float il0 = 1.f / lsum0;
    const float il1 = 1.f / lsum1;
    const int r0 = q0 + ar;
#pragma unroll
    for (int nt = 0; nt < NDT; nt++) {
        const int col = nt * 8 + lc * 2;
        if (col < 99) {
            unsigned h, l;
            long F = (long)h_ * (S_LEN * DHEAD) + (long)r0 * DHEAD + col;
            long R = (long)b_ * S_LEN + F / HIDDEN;
            int cu = (int)(F % HIDDEN) >> 1;
            split2(oacc[nt][0] * il0, oacc[nt][1] * il0, h, l);
            og[R * PPAIR + cu] = make_uint2(h, l);
            F += 8 * DHEAD;
            R = (long)b_ * S_LEN + F / HIDDEN;
            cu = (int)(F % HIDDEN) >> 1;
            split2(oacc[nt][2] * il1, oacc[nt][3] * il1, h, l);
            og[R * PPAIR + cu] = make_uint2(h, l);
        }
    }
}

// ---------------------------------------------------------------------------
// Launch
// ---------------------------------------------------------------------------
extern "C" void kernel_launch(void* const* d_in, const int* in_sizes, int n_in,
                              void* d_out, int out_size)
{
    const float* x     = (const float*)d_in[0];
    const float* alibi = (const float*)d_in[1];
    const float* mask  = (const float*)d_in[2];
    const float* wts[4] = { (const float*)d_in[3], (const float*)d_in[4],
                            (const float*)d_in[5], (const float*)d_in[6] };
    const int*   li    = (const int*)d_in[7];
    float* out = (float*)d_out;

    uint2 *xb, *wb, *qb, *kb, *vtb, *ob;
    cudaGetSymbolAddress((void**)&xb,  g_x);
    cudaGetSymbolAddress((void**)&wb,  g_w);
    cudaGetSymbolAddress((void**)&qb,  g_q);
    cudaGetSymbolAddress((void**)&kb,  g_k);
    cudaGetSymbolAddress((void**)&vtb, g_vt);
    cudaGetSymbolAddress((void**)&ob,  g_o);

    cudaFuncSetAttribute(flash_kernel,
                         cudaFuncAttributeMaxDynamicSharedMemorySize, FL_SMEM_BYTES);
    cudaFuncSetAttribute(gemm_pipe_kernel,
                         cudaFuncAttributeMaxDynamicSharedMemorySize, GT_SMEM);

    // prep
    init_pads_kernel<<<768, 256>>>(qb, kb, vtb, ob);
    const int totX = M_TOT * PPAIR;
    const int totW = PROWSW * PPAIR;
    split_pad_kernel<<<(totX + 255) / 256, 256>>>(x, xb, M_TOT, HIDDEN, totX);
    for (int i = 0; i < 4; i++)
        split_pad_kernel<<<(totW + 255) / 256, 256>>>(
            wts[i], wb + (long)i * totW, HIDDEN, HIDDEN, totW);

    dim3 gg(M_TOT / 128, PROWSW / 128);   // (64, 10)
    gemm_pipe_kernel<<<gg, 512, GT_SMEM>>>(xb, wb + 0L * totW, nullptr, qb, nullptr, 1);
    gemm_pipe_kernel<<<gg, 512, GT_SMEM>>>(xb, wb + 1L * totW, nullptr, kb, nullptr, 1);
    gemm_pipe_kernel<<<gg, 512, GT_SMEM>>>(xb, wb + 2L * totW, nullptr, nullptr, vtb, 3);

    flash_kernel<<<dim3(BH, S_LEN / 128), 256, FL_SMEM_BYTES>>>(
        alibi, mask, li, qb, kb, vtb, ob);

    gemm_pipe_kernel<<<gg, 512, GT_SMEM>>>(ob, wb + 3L * totW, out, nullptr, nullptr, 0);
}